// round 6
// baseline (speedup 1.0000x reference)
#include <cuda_runtime.h>
#include <cstdint>

#define DEVI __device__ __forceinline__

constexpr int NQ = 131072;   // queries
constexpr int MN = 8192;     // tree nodes
constexpr float F_EPS = 1e-6f;
constexpr float F_BIG = 1e9f;

// ---------------- shared-memory layout (float word offsets) ------------------
// All mainloop operands are K-CONTIGUOUS so fp32x2 pairs load directly:
//   h stored [row][k]   (per-group block, stride 100)
//   W2 stored transposed [col][k], 128 cols (100..127 zero), stride 108
//   W3 stored transposed [col][k],  32 cols ( 30..31  zero), stride 108
// stride 108: col*108 % 32 = 12*col -> lanes' cols hit distinct bank quads
constexpr int OFF_W1  = 0;        // [2][100] -> 200
constexpr int OFF_B1  = 200;      // 100 -> 300, pad 304
constexpr int OFF_W2T = 304;      // 128*108 = 13824 -> 14128
constexpr int OFF_B2  = 14128;    // 128 -> 14256
constexpr int OFF_W3T = 14256;    // 32*108 = 3456 -> 17712
constexpr int OFF_B3  = 17712;    // 32 -> 17744
constexpr int OFF_W4  = 17744;    // [32][2] = 64 -> 17808
constexpr int OFF_B4  = 17808;    // 2 pad 16 -> 17824
constexpr int OFF_H   = 17824;    // per-warp h block: [8 rows][100 k]
constexpr int H_GSTRIDE = 800;
constexpr int R_ROWS  = 8;        // rows per group (group = one warp)
constexpr int GROUPS  = 17;       // warps per CTA
constexpr int MLP_BLOCK = 544;
constexpr int MLP_GRID  = 152;
constexpr int SMEM_FLOATS = OFF_H + GROUPS * H_GSTRIDE;   // 31424
constexpr int SMEM_BYTES  = SMEM_FLOATS * 4;              // 125,696 B

constexpr int CHUNKS = (MN + NQ) / R_ROWS;            // 17408 (exact)
constexpr int SLOTS  = MLP_GRID * GROUPS;             // 2584
constexpr int ROUNDS = (CHUNKS + SLOTS - 1) / SLOTS;  // 7 -> 96.2% fill

// ---------------- scratch (device globals: no allocation allowed) ------------
__device__ float2 g_emb[MN];     // transformed node embeddings
__device__ float2 g_qx[NQ];      // transformed queries
__device__ float4 g_node2[MN];   // (prob2.x, prob2.y, has_child, 0)

typedef unsigned long long u64;

// d.lo += a.lo*b.lo ; d.hi += a.hi*b.hi   (sm_100+ packed fp32)
DEVI void fma2(u64 &d, u64 a, u64 b) {
    asm("fma.rn.f32x2 %0, %1, %2, %0;" : "+l"(d) : "l"(a), "l"(b));
}
DEVI void unpack2(u64 v, float &lo, float &hi) {
    unsigned a, b;
    asm("mov.b64 {%0, %1}, %2;" : "=r"(a), "=r"(b) : "l"(v));
    lo = __uint_as_float(a); hi = __uint_as_float(b);
}

// torch.nn.PairwiseDistance: ||a - b + eps||_2
DEVI float pdist(float ax, float ay, float bx, float by) {
    float dx = ax - bx + F_EPS;
    float dy = ay - by + F_EPS;
    return sqrtf(fmaf(dx, dx, dy * dy));
}

// ---------------- kernel 1: fused node+query MLP ------------------------------
// Work unit = 8-row chunk per WARP. Lane q owns cols {q, q+32, q+64, q+96} of
// layer 2 (128-padded) and col q of layer 3, for all 8 rows. K-paired fp32x2:
// even-k partial in lo, odd-k in hi, folded once at the end. h broadcast to the
// whole warp from its own SMEM block; weights k-contiguous LDS.128.
__global__ void __launch_bounds__(MLP_BLOCK, 1)
mlp_all_kernel(const float* __restrict__ x, const float* __restrict__ nd,
               const float* __restrict__ W1, const float* __restrict__ b1,
               const float* __restrict__ W2, const float* __restrict__ b2,
               const float* __restrict__ W3, const float* __restrict__ b3,
               const float* __restrict__ W4, const float* __restrict__ b4) {
    extern __shared__ float sm[];
    const int t = threadIdx.x;

    // zero weight region (covers all zero-pad cols/rows), then stage transposed
    for (int i = t; i < OFF_H; i += MLP_BLOCK) sm[i] = 0.f;
    __syncthreads();
    for (int i = t; i < 200; i += MLP_BLOCK) sm[OFF_W1 + i] = W1[i];
    for (int i = t; i < 100; i += MLP_BLOCK) sm[OFF_B1 + i] = b1[i];
    for (int i = t; i < 10000; i += MLP_BLOCK) {      // W2T[c][k] = W2[k][c]
        int k = i / 100, c = i - k * 100;
        sm[OFF_W2T + c * 108 + k] = W2[i];
    }
    for (int j = t; j < 100; j += MLP_BLOCK) sm[OFF_B2 + j] = b2[j];
    for (int i = t; i < 3000; i += MLP_BLOCK) {       // W3T[c][k] = W3[k][c]
        int k = i / 30, c = i - k * 30;
        sm[OFF_W3T + c * 108 + k] = W3[i];
    }
    for (int i = t; i < 30; i += MLP_BLOCK) sm[OFF_B3 + i] = b3[i];
    for (int i = t; i < 60; i += MLP_BLOCK) sm[OFF_W4 + i] = W4[i];
    if (t < 2) sm[OFF_B4 + t] = b4[t];
    __syncthreads();

    const int lane = t & 31;
    const int wid  = t >> 5;                  // group == warp
    float* hg = sm + OFF_H + wid * H_GSTRIDE;
    const float* w2c0 = sm + OFF_W2T + lane * 108;    // cols q+32j at +32j*108
    const float* w3c  = sm + OFF_W3T + lane * 108;

    int chunk = blockIdx.x * GROUPS + wid;

    for (int rnd = 0; rnd < ROUNDS; rnd++, chunk += SLOTS) {
        if (chunk >= CHUNKS) continue;        // warp-uniform
        const int row0 = chunk * R_ROWS;

        // ---- layer 1 (2 -> 100): lane computes h1[0..7][k], k = q+32j ------
        {
            const bool isnode = row0 < MN;    // MN%8==0: never straddles
            const float4* src = (const float4*)(
                (isnode ? nd : x) + (size_t)(isnode ? row0 : row0 - MN) * 2);
            float4 v0 = __ldg(src + 0), v1 = __ldg(src + 1);
            float4 v2 = __ldg(src + 2), v3 = __ldg(src + 3);
            float x0[8] = {v0.x, v0.z, v1.x, v1.z, v2.x, v2.z, v3.x, v3.z};
            float x1[8] = {v0.y, v0.w, v1.y, v1.w, v2.y, v2.w, v3.y, v3.w};
            #pragma unroll
            for (int j = 0; j < 4; j++) {
                int k = lane + 32 * j;
                if (k < 100) {
                    float wa = sm[OFF_W1 + k];
                    float wb = sm[OFF_W1 + 100 + k];
                    float bb = sm[OFF_B1 + k];
                    #pragma unroll
                    for (int r = 0; r < 8; r++)
                        hg[r * 100 + k] =
                            fmaxf(fmaf(x0[r], wa, fmaf(x1[r], wb, bb)), 0.f);
                }
            }
        }
        __syncwarp();

        // ---- layer 2 (100 -> 128pad): 4 cols x 8 rows, k-paired ------------
        u64 acc[4][8];
        #pragma unroll
        for (int j = 0; j < 4; j++)
            #pragma unroll
            for (int r = 0; r < 8; r++) acc[j][r] = 0ull;
        #pragma unroll 1
        for (int k = 0; k < 100; k += 4) {
            ulonglong2 w[4];
            #pragma unroll
            for (int j = 0; j < 4; j++)
                w[j] = *(const ulonglong2*)(w2c0 + 32 * 108 * j + k);
            #pragma unroll
            for (int r = 0; r < 8; r++) {
                ulonglong2 hq = *(const ulonglong2*)(hg + r * 100 + k);
                #pragma unroll
                for (int j = 0; j < 4; j++) {
                    fma2(acc[j][r], hq.x, w[j].x);
                    fma2(acc[j][r], hq.y, w[j].y);
                }
            }
        }
        __syncwarp();   // h1 reads done before h2 overwrite

        #pragma unroll
        for (int j = 0; j < 4; j++) {
            int c = lane + 32 * j;
            if (c < 100) {
                float bb = sm[OFF_B2 + c];
                #pragma unroll
                for (int r = 0; r < 8; r++) {
                    float lo, hi; unpack2(acc[j][r], lo, hi);
                    hg[r * 100 + c] = fmaxf(lo + hi + bb, 0.f);
                }
            }
        }
        __syncwarp();

        // ---- layer 3 (100 -> 30 pad 32): col q x 8 rows, k-paired ----------
        u64 a3[8];
        #pragma unroll
        for (int r = 0; r < 8; r++) a3[r] = 0ull;
        #pragma unroll 1
        for (int k = 0; k < 100; k += 4) {
            ulonglong2 w = *(const ulonglong2*)(w3c + k);
            #pragma unroll
            for (int r = 0; r < 8; r++) {
                ulonglong2 hq = *(const ulonglong2*)(hg + r * 100 + k);
                fma2(a3[r], hq.x, w.x);
                fma2(a3[r], hq.y, w.y);
            }
        }
        float out3[8];
        {
            float b3v = sm[OFF_B3 + lane];    // lanes 30,31: zero pad
            #pragma unroll
            for (int r = 0; r < 8; r++) {
                float lo, hi; unpack2(a3[r], lo, hi);
                out3[r] = fmaxf(lo + hi + b3v, 0.f);
            }
        }

        // ---- layer 4 (30 -> 2): lane's col contribution, warp-reduced ------
        float2 w4 = *(const float2*)(sm + OFF_W4 + 2 * lane);  // rows 30,31 zero
        float o0[8], o1[8];
        #pragma unroll
        for (int r = 0; r < 8; r++) {
            o0[r] = out3[r] * w4.x;
            o1[r] = out3[r] * w4.y;
        }
        #pragma unroll
        for (int r = 0; r < 8; r++) {
            #pragma unroll
            for (int s = 1; s < 32; s <<= 1) {
                o0[r] += __shfl_xor_sync(0xffffffffu, o0[r], s);
                o1[r] += __shfl_xor_sync(0xffffffffu, o1[r], s);
            }
        }
        if (lane < 8) {
            // lane q emits row q (static selects, no local-mem indexing)
            int q = lane;
            float s0 = (q == 0) ? o0[0] : (q == 1) ? o0[1] : (q == 2) ? o0[2] :
                       (q == 3) ? o0[3] : (q == 4) ? o0[4] : (q == 5) ? o0[5] :
                       (q == 6) ? o0[6] : o0[7];
            float s1 = (q == 0) ? o1[0] : (q == 1) ? o1[1] : (q == 2) ? o1[2] :
                       (q == 3) ? o1[3] : (q == 4) ? o1[4] : (q == 5) ? o1[5] :
                       (q == 6) ? o1[6] : o1[7];
            float2 ov = make_float2(s0 + sm[OFF_B4 + 0], s1 + sm[OFF_B4 + 1]);
            int row = row0 + q;
            if (row < MN) g_emb[row] = ov;
            else          g_qx[row - MN] = ov;
        }
        __syncwarp();
    }
}

// ---------------- kernel 2: per-node prob2 / has_child (query-independent) ---
__global__ void precompute_kernel(const float* __restrict__ node_classes,
                                  const int* __restrict__ children) {
    int i = blockIdx.x * blockDim.x + threadIdx.x;
    if (i >= MN) return;
    const int4* ch4 = (const int4*)children;
    int4 c0 = ch4[2 * i], c1 = ch4[2 * i + 1];
    int ci[8] = {c0.x, c0.y, c0.z, c0.w, c1.x, c1.y, c1.z, c1.w};
    float2 e = g_emb[i];
    float d[8]; bool any = false;
    #pragma unroll
    for (int k = 0; k < 8; k++) {
        int c = ci[k];
        if (c >= 0) {
            float2 ec = g_emb[c];
            d[k] = pdist(e.x, e.y, ec.x, ec.y);   // dist(emb[cur], c_emb)
            any = true;
        } else d[k] = F_BIG;
    }
    float4 r = make_float4(0.f, 0.f, 0.f, 0.f);
    if (any) {
        float mn = d[0];
        #pragma unroll
        for (int k = 1; k < 8; k++) mn = fminf(mn, d[k]);
        float S = 0.f, m0 = 0.f, m1 = 0.f;
        #pragma unroll
        for (int k = 0; k < 8; k++) {
            float ek = expf(-(d[k] - mn));
            S += ek;
            int c = ci[k];
            if (c >= 0) {
                m0 = fmaf(ek, node_classes[2 * c + 0], m0);
                m1 = fmaf(ek, node_classes[2 * c + 1], m1);
            }
        }
        m0 /= S; m1 /= S;
        r.x = logf(fmaxf(m0, 1e-30f));
        r.y = logf(fmaxf(m1, 1e-30f));
        r.z = 1.f;
    }
    g_node2[i] = r;
}

// ---------------- kernel 3: tree traversal (no smem, high occupancy) ---------
__global__ void __launch_bounds__(256)
traverse_kernel(const int* __restrict__ children, float* __restrict__ out) {
    const int q = blockIdx.x * 256 + threadIdx.x;   // grid covers NQ exactly
    const float2 qx = g_qx[q];
    const float q0 = qx.x, q1 = qx.y;
    const int4* ch4 = (const int4*)children;

    int cur = 0;
    float prob = 0.f, o0 = 0.f, o1 = 0.f;
    for (int t = 0; t < 16; t++) {
        int4 c0 = __ldg(ch4 + 2 * cur);
        int4 c1 = __ldg(ch4 + 2 * cur + 1);
        int ci[8] = {c0.x, c0.y, c0.z, c0.w, c1.x, c1.y, c1.z, c1.w};
        float2 e = g_emb[cur];
        float d0 = pdist(e.x, e.y, q0, q1);
        float d[8];
        #pragma unroll
        for (int k = 0; k < 8; k++) {
            int c = ci[k];
            if (c >= 0) {
                float2 ec = g_emb[c];
                d[k] = pdist(ec.x, ec.y, q0, q1);
            } else d[k] = F_BIG;
        }
        // argmax(log_softmax(-d)) == first-occurrence argmin(d)
        float best = d0; int bi = 0;
        #pragma unroll
        for (int k = 0; k < 8; k++) { if (d[k] < best) { best = d[k]; bi = k + 1; } }
        float S = __expf(-(d0 - best));
        #pragma unroll
        for (int k = 0; k < 8; k++) S += __expf(-(d[k] - best));  // pad: exp(-1e9)=0
        float mp = -__logf(S);     // max of log_softmax
        prob += mp;
        if (t == 0) prob += mp;    // source quirk: first iter adds max_prob twice
        if (bi == 0) {
            float4 n2 = g_node2[cur];
            if (n2.z != 0.f) { o0 = prob + n2.x; o1 = prob + n2.y; }
            else             { o0 = prob;        o1 = prob;        }
            break;
        }
        cur = ci[bi - 1];
    }
    ((float2*)out)[q] = make_float2(o0, o1);
}

// ---------------- launch ------------------------------------------------------
extern "C" void kernel_launch(void* const* d_in, const int* in_sizes, int n_in,
                              void* d_out, int out_size) {
    const float* x  = (const float*)d_in[0];
    const float* nd = (const float*)d_in[1];
    const float* nc = (const float*)d_in[2];
    const int*   ch = (const int*)  d_in[3];
    const float* W1 = (const float*)d_in[4];
    const float* b1 = (const float*)d_in[5];
    const float* W2 = (const float*)d_in[6];
    const float* b2 = (const float*)d_in[7];
    const float* W3 = (const float*)d_in[8];
    const float* b3 = (const float*)d_in[9];
    const float* W4 = (const float*)d_in[10];
    const float* b4 = (const float*)d_in[11];

    cudaFuncSetAttribute(mlp_all_kernel,
                         cudaFuncAttributeMaxDynamicSharedMemorySize, SMEM_BYTES);

    mlp_all_kernel<<<MLP_GRID, MLP_BLOCK, SMEM_BYTES>>>(x, nd,
                                                        W1, b1, W2, b2,
                                                        W3, b3, W4, b4);
    precompute_kernel<<<MN / 256, 256>>>(nc, ch);
    traverse_kernel<<<NQ / 256, 256>>>(ch, (float*)d_out);
}

// round 7
// speedup vs baseline: 1.1938x; 1.1938x over previous
#include <cuda_runtime.h>
#include <cstdint>

#define DEVI __device__ __forceinline__

constexpr int NQ = 131072;   // queries
constexpr int MN = 8192;     // tree nodes
constexpr float F_EPS = 1e-6f;
constexpr float F_BIG = 1e9f;

// ---------------- shared-memory layout (float word offsets) ------------------
// W2 natural [k][c] padded to 128 cols (100..127 zero): per-k weight load is
// LDS.32 at bank==lane -> conflict-free. W3 natural [k][c] padded to 32 cols.
// h per-warp block [k][8 rows]: row-pair LDS.64 (whole-warp broadcast) is a
// ready fp32x2 operand -> zero h-side pack instructions.
constexpr int OFF_W1 = 0;        // [2][100] -> 200
constexpr int OFF_B1 = 200;      // 100 -> 300, pad 304
constexpr int OFF_W2 = 304;      // [100][128] = 12800 -> 13104
constexpr int OFF_B2 = 13104;    // 128 -> 13232
constexpr int OFF_W3 = 13232;    // [100][32] = 3200 -> 16432
constexpr int OFF_B3 = 16432;    // 32 -> 16464
constexpr int OFF_W4 = 16464;    // [32][2] = 64 -> 16528
constexpr int OFF_B4 = 16528;    // 2 pad 16 -> 16544
constexpr int OFF_H  = 16544;    // per-warp h block: [100 k][8 rows]
constexpr int H_GSTRIDE = 800;
constexpr int R_ROWS  = 8;       // rows per group (group = one warp)
constexpr int GROUPS  = 20;      // warps per CTA
constexpr int MLP_BLOCK = 640;
constexpr int MLP_GRID  = 152;
constexpr int SMEM_FLOATS = OFF_H + GROUPS * H_GSTRIDE;   // 32544
constexpr int SMEM_BYTES  = SMEM_FLOATS * 4;              // 130,176 B

constexpr int CHUNKS = (MN + NQ) / R_ROWS;            // 17408 (exact)
constexpr int SLOTS  = MLP_GRID * GROUPS;             // 3040
constexpr int ROUNDS = (CHUNKS + SLOTS - 1) / SLOTS;  // 6 -> 95.4% fill

// ---------------- scratch (device globals: no allocation allowed) ------------
__device__ float2 g_emb[MN];     // transformed node embeddings
__device__ float2 g_qx[NQ];      // transformed queries
__device__ float4 g_node2[MN];   // (prob2.x, prob2.y, has_child, 0)

typedef unsigned long long u64;

DEVI u64 pack2(float lo, float hi) {
    u64 r;
    asm("mov.b64 %0, {%1, %2};"
        : "=l"(r) : "r"(__float_as_uint(lo)), "r"(__float_as_uint(hi)));
    return r;
}
DEVI void unpack2(u64 v, float &lo, float &hi) {
    unsigned a, b;
    asm("mov.b64 {%0, %1}, %2;" : "=r"(a), "=r"(b) : "l"(v));
    lo = __uint_as_float(a); hi = __uint_as_float(b);
}
// d.lo += a.lo*b.lo ; d.hi += a.hi*b.hi   (sm_100+ packed fp32)
DEVI void fma2(u64 &d, u64 a, u64 b) {
    asm("fma.rn.f32x2 %0, %1, %2, %0;" : "+l"(d) : "l"(a), "l"(b));
}

// torch.nn.PairwiseDistance: ||a - b + eps||_2
DEVI float pdist(float ax, float ay, float bx, float by) {
    float dx = ax - bx + F_EPS;
    float dy = ay - by + F_EPS;
    return sqrtf(fmaf(dx, dx, dy * dy));
}

// ---------------- kernel 1: fused node+query MLP ------------------------------
// Work unit = 8-row chunk per WARP. Lane q owns layer-2 cols {q+32j : j=0..3}
// of the 128-padded W2 and layer-3 col q of the 32-padded W3, for all 8 rows.
// Accumulators are ROW-PAIRED fp32x2: lo = row 2rp, hi = row 2rp+1, so the h
// operand is a direct LDS.64 from the [k][8] block and only the (scalar,
// lane-private) weight needs a 2-MOV duplication.
__global__ void __launch_bounds__(MLP_BLOCK, 1)
mlp_all_kernel(const float* __restrict__ x, const float* __restrict__ nd,
               const float* __restrict__ W1, const float* __restrict__ b1,
               const float* __restrict__ W2, const float* __restrict__ b2,
               const float* __restrict__ W3, const float* __restrict__ b3,
               const float* __restrict__ W4, const float* __restrict__ b4) {
    extern __shared__ float sm[];
    const int t = threadIdx.x;

    // zero weight region (covers all zero-pad cols), then stage
    for (int i = t; i < OFF_H; i += MLP_BLOCK) sm[i] = 0.f;
    __syncthreads();
    for (int i = t; i < 200; i += MLP_BLOCK) sm[OFF_W1 + i] = W1[i];
    for (int i = t; i < 100; i += MLP_BLOCK) sm[OFF_B1 + i] = b1[i];
    for (int i = t; i < 10000; i += MLP_BLOCK) {      // [100][128] pad
        int k = i / 100, c = i - k * 100;
        sm[OFF_W2 + k * 128 + c] = W2[i];
    }
    for (int j = t; j < 100; j += MLP_BLOCK) sm[OFF_B2 + j] = b2[j];
    for (int i = t; i < 3000; i += MLP_BLOCK) {       // [100][32] pad
        int k = i / 30, c = i - k * 30;
        sm[OFF_W3 + k * 32 + c] = W3[i];
    }
    for (int i = t; i < 30; i += MLP_BLOCK) sm[OFF_B3 + i] = b3[i];
    for (int i = t; i < 60; i += MLP_BLOCK) sm[OFF_W4 + i] = W4[i];
    if (t < 2) sm[OFF_B4 + t] = b4[t];
    __syncthreads();

    const int lane = t & 31;
    const int wid  = t >> 5;                  // group == warp
    float* hg = sm + OFF_H + wid * H_GSTRIDE;

    int chunk = blockIdx.x * GROUPS + wid;

    for (int rnd = 0; rnd < ROUNDS; rnd++, chunk += SLOTS) {
        if (chunk >= CHUNKS) continue;        // warp-uniform
        const int row0 = chunk * R_ROWS;

        // ---- layer 1 (2 -> 100): lane computes h1[k][0..7], k = lane+32j ---
        {
            const bool isnode = row0 < MN;    // MN%8==0: never straddles
            const float4* src = (const float4*)(
                (isnode ? nd : x) + (size_t)(isnode ? row0 : row0 - MN) * 2);
            float4 v0 = __ldg(src + 0), v1 = __ldg(src + 1);
            float4 v2 = __ldg(src + 2), v3 = __ldg(src + 3);
            float x0[8] = {v0.x, v0.z, v1.x, v1.z, v2.x, v2.z, v3.x, v3.z};
            float x1[8] = {v0.y, v0.w, v1.y, v1.w, v2.y, v2.w, v3.y, v3.w};
            #pragma unroll
            for (int j = 0; j < 4; j++) {
                int k = lane + 32 * j;
                if (k < 100) {
                    float wa = sm[OFF_W1 + k];
                    float wb = sm[OFF_W1 + 100 + k];
                    float bb = sm[OFF_B1 + k];
                    float hv[8];
                    #pragma unroll
                    for (int r = 0; r < 8; r++)
                        hv[r] = fmaxf(fmaf(x0[r], wa, fmaf(x1[r], wb, bb)), 0.f);
                    *(float4*)(hg + k * 8)     = make_float4(hv[0], hv[1], hv[2], hv[3]);
                    *(float4*)(hg + k * 8 + 4) = make_float4(hv[4], hv[5], hv[6], hv[7]);
                }
            }
        }
        __syncwarp();

        // ---- layer 2 (100 -> 128pad): 4 cols x 4 row-pairs per lane --------
        u64 acc[4][4];
        #pragma unroll
        for (int j = 0; j < 4; j++)
            #pragma unroll
            for (int rp = 0; rp < 4; rp++) acc[j][rp] = 0ull;
        const float* w2l = sm + OFF_W2 + lane;
        #pragma unroll 2
        for (int k = 0; k < 100; k++) {
            const float* wr = w2l + k * 128;
            u64 w[4];
            #pragma unroll
            for (int j = 0; j < 4; j++) {
                float wv = wr[32 * j];                 // LDS.32, bank==lane
                w[j] = pack2(wv, wv);
            }
            u64 hp[4];
            #pragma unroll
            for (int rp = 0; rp < 4; rp++)
                hp[rp] = *(const u64*)(hg + k * 8 + 2 * rp);  // broadcast LDS.64
            #pragma unroll
            for (int j = 0; j < 4; j++)
                #pragma unroll
                for (int rp = 0; rp < 4; rp++)
                    fma2(acc[j][rp], hp[rp], w[j]);
        }
        __syncwarp();   // h1 reads done before h2 overwrite

        // relu + bias + write h2 (only real cols < 100)
        #pragma unroll
        for (int j = 0; j < 4; j++) {
            int c = lane + 32 * j;
            if (c < 100) {
                float bb = sm[OFF_B2 + c];
                float hv[8];
                #pragma unroll
                for (int rp = 0; rp < 4; rp++) {
                    float lo, hi; unpack2(acc[j][rp], lo, hi);
                    hv[2 * rp]     = fmaxf(lo + bb, 0.f);
                    hv[2 * rp + 1] = fmaxf(hi + bb, 0.f);
                }
                *(float4*)(hg + c * 8)     = make_float4(hv[0], hv[1], hv[2], hv[3]);
                *(float4*)(hg + c * 8 + 4) = make_float4(hv[4], hv[5], hv[6], hv[7]);
            }
        }
        __syncwarp();

        // ---- layer 3 (100 -> 30 pad 32): col q x 4 row-pairs ---------------
        u64 a3[4];
        #pragma unroll
        for (int rp = 0; rp < 4; rp++) a3[rp] = 0ull;
        const float* w3l = sm + OFF_W3 + lane;
        #pragma unroll 2
        for (int k = 0; k < 100; k++) {
            float wv = w3l[k * 32];                    // LDS.32, bank==lane
            u64 w = pack2(wv, wv);
            #pragma unroll
            for (int rp = 0; rp < 4; rp++) {
                u64 hp = *(const u64*)(hg + k * 8 + 2 * rp);
                fma2(a3[rp], hp, w);
            }
        }
        float out3[8];
        {
            float b3v = sm[OFF_B3 + lane];             // lanes 30,31: zero pad
            #pragma unroll
            for (int rp = 0; rp < 4; rp++) {
                float lo, hi; unpack2(a3[rp], lo, hi);
                out3[2 * rp]     = fmaxf(lo + b3v, 0.f);
                out3[2 * rp + 1] = fmaxf(hi + b3v, 0.f);
            }
        }

        // ---- layer 4 (30 -> 2): lane's col contribution, warp-reduced ------
        float2 w4 = *(const float2*)(sm + OFF_W4 + 2 * lane);  // rows 30,31 zero
        float o0[8], o1[8];
        #pragma unroll
        for (int r = 0; r < 8; r++) {
            o0[r] = out3[r] * w4.x;
            o1[r] = out3[r] * w4.y;
        }
        #pragma unroll
        for (int r = 0; r < 8; r++) {
            #pragma unroll
            for (int s = 1; s < 32; s <<= 1) {
                o0[r] += __shfl_xor_sync(0xffffffffu, o0[r], s);
                o1[r] += __shfl_xor_sync(0xffffffffu, o1[r], s);
            }
        }
        if (lane < 8) {
            // lane q emits row q (static selects, no local-mem indexing)
            int q = lane;
            float s0 = (q == 0) ? o0[0] : (q == 1) ? o0[1] : (q == 2) ? o0[2] :
                       (q == 3) ? o0[3] : (q == 4) ? o0[4] : (q == 5) ? o0[5] :
                       (q == 6) ? o0[6] : o0[7];
            float s1 = (q == 0) ? o1[0] : (q == 1) ? o1[1] : (q == 2) ? o1[2] :
                       (q == 3) ? o1[3] : (q == 4) ? o1[4] : (q == 5) ? o1[5] :
                       (q == 6) ? o1[6] : o1[7];
            float2 ov = make_float2(s0 + sm[OFF_B4 + 0], s1 + sm[OFF_B4 + 1]);
            int row = row0 + q;
            if (row < MN) g_emb[row] = ov;
            else          g_qx[row - MN] = ov;
        }
        __syncwarp();
    }
}

// ---------------- kernel 2: per-node prob2 / has_child (query-independent) ---
__global__ void precompute_kernel(const float* __restrict__ node_classes,
                                  const int* __restrict__ children) {
    int i = blockIdx.x * blockDim.x + threadIdx.x;
    if (i >= MN) return;
    const int4* ch4 = (const int4*)children;
    int4 c0 = ch4[2 * i], c1 = ch4[2 * i + 1];
    int ci[8] = {c0.x, c0.y, c0.z, c0.w, c1.x, c1.y, c1.z, c1.w};
    float2 e = g_emb[i];
    float d[8]; bool any = false;
    #pragma unroll
    for (int k = 0; k < 8; k++) {
        int c = ci[k];
        if (c >= 0) {
            float2 ec = g_emb[c];
            d[k] = pdist(e.x, e.y, ec.x, ec.y);   // dist(emb[cur], c_emb)
            any = true;
        } else d[k] = F_BIG;
    }
    float4 r = make_float4(0.f, 0.f, 0.f, 0.f);
    if (any) {
        float mn = d[0];
        #pragma unroll
        for (int k = 1; k < 8; k++) mn = fminf(mn, d[k]);
        float S = 0.f, m0 = 0.f, m1 = 0.f;
        #pragma unroll
        for (int k = 0; k < 8; k++) {
            float ek = expf(-(d[k] - mn));
            S += ek;
            int c = ci[k];
            if (c >= 0) {
                m0 = fmaf(ek, node_classes[2 * c + 0], m0);
                m1 = fmaf(ek, node_classes[2 * c + 1], m1);
            }
        }
        m0 /= S; m1 /= S;
        r.x = logf(fmaxf(m0, 1e-30f));
        r.y = logf(fmaxf(m1, 1e-30f));
        r.z = 1.f;
    }
    g_node2[i] = r;
}

// ---------------- kernel 3: tree traversal (no smem, high occupancy) ---------
__global__ void __launch_bounds__(256)
traverse_kernel(const int* __restrict__ children, float* __restrict__ out) {
    const int q = blockIdx.x * 256 + threadIdx.x;   // grid covers NQ exactly
    const float2 qx = g_qx[q];
    const float q0 = qx.x, q1 = qx.y;
    const int4* ch4 = (const int4*)children;

    int cur = 0;
    float prob = 0.f, o0 = 0.f, o1 = 0.f;
    for (int t = 0; t < 16; t++) {
        int4 c0 = __ldg(ch4 + 2 * cur);
        int4 c1 = __ldg(ch4 + 2 * cur + 1);
        int ci[8] = {c0.x, c0.y, c0.z, c0.w, c1.x, c1.y, c1.z, c1.w};
        float2 e = g_emb[cur];
        float d0 = pdist(e.x, e.y, q0, q1);
        float d[8];
        #pragma unroll
        for (int k = 0; k < 8; k++) {
            int c = ci[k];
            if (c >= 0) {
                float2 ec = g_emb[c];
                d[k] = pdist(ec.x, ec.y, q0, q1);
            } else d[k] = F_BIG;
        }
        // argmax(log_softmax(-d)) == first-occurrence argmin(d)
        float best = d0; int bi = 0;
        #pragma unroll
        for (int k = 0; k < 8; k++) { if (d[k] < best) { best = d[k]; bi = k + 1; } }
        float S = __expf(-(d0 - best));
        #pragma unroll
        for (int k = 0; k < 8; k++) S += __expf(-(d[k] - best));  // pad: exp(-1e9)=0
        float mp = -__logf(S);     // max of log_softmax
        prob += mp;
        if (t == 0) prob += mp;    // source quirk: first iter adds max_prob twice
        if (bi == 0) {
            float4 n2 = g_node2[cur];
            if (n2.z != 0.f) { o0 = prob + n2.x; o1 = prob + n2.y; }
            else             { o0 = prob;        o1 = prob;        }
            break;
        }
        cur = ci[bi - 1];
    }
    ((float2*)out)[q] = make_float2(o0, o1);
}

// ---------------- launch ------------------------------------------------------
extern "C" void kernel_launch(void* const* d_in, const int* in_sizes, int n_in,
                              void* d_out, int out_size) {
    const float* x  = (const float*)d_in[0];
    const float* nd = (const float*)d_in[1];
    const float* nc = (const float*)d_in[2];
    const int*   ch = (const int*)  d_in[3];
    const float* W1 = (const float*)d_in[4];
    const float* b1 = (const float*)d_in[5];
    const float* W2 = (const float*)d_in[6];
    const float* b2 = (const float*)d_in[7];
    const float* W3 = (const float*)d_in[8];
    const float* b3 = (const float*)d_in[9];
    const float* W4 = (const float*)d_in[10];
    const float* b4 = (const float*)d_in[11];

    cudaFuncSetAttribute(mlp_all_kernel,
                         cudaFuncAttributeMaxDynamicSharedMemorySize, SMEM_BYTES);

    mlp_all_kernel<<<MLP_GRID, MLP_BLOCK, SMEM_BYTES>>>(x, nd,
                                                        W1, b1, W2, b2,
                                                        W3, b3, W4, b4);
    precompute_kernel<<<MN / 256, 256>>>(nc, ch);
    traverse_kernel<<<NQ / 256, 256>>>(ch, (float*)d_out);
}